// round 1
// baseline (speedup 1.0000x reference)
#include <cuda_runtime.h>
#include <cstdint>
#include <cstddef>

// Problem dims (fixed by the dataset)
#define D_DIM 1024
#define M_TOT 32768            // B*S = 32*1024
#define N_TOT 3072             // 3*D
#define K_TOT 1024             // D
#define RANK  5

// GEMM tiling
#define BM 128
#define BN 128
#define BK 32
#define STRIDE 36              // smem row stride in floats (pad 32 -> 36, conflict-free)
#define ASZ (BM * STRIDE)      // floats per (matrix, stage)
#define SMEM_BYTES (4 * ASZ * 4)  // 2 stages * (A + B) * 4B = 73728

// Effective weight W + delta, computed once per launch. 12 MB device global.
__device__ float g_Wd[(size_t)N_TOT * K_TOT];

// ---------------------------------------------------------------------------
// Prep: Wd[n][k] = W[n][k] + (LoRA delta on rows [D, 3D))
// ---------------------------------------------------------------------------
__global__ void prep_wd(const float* __restrict__ W,
                        const float* __restrict__ A0, const float* __restrict__ A1,
                        const float* __restrict__ B0, const float* __restrict__ B1,
                        const float* __restrict__ s0p, const float* __restrict__ s1p)
{
    int idx = blockIdx.x * blockDim.x + threadIdx.x;
    if (idx >= N_TOT * K_TOT) return;
    int n = idx / K_TOT;
    int k = idx - n * K_TOT;
    float w = W[idx];
    if (n >= D_DIM) {
        if (n < 2 * D_DIM) {
            int r = n - D_DIM;
            float acc = 0.f;
#pragma unroll
            for (int j = 0; j < RANK; j++)
                acc += B0[r * RANK + j] * A0[j * K_TOT + k];
            w += s0p[0] * acc;
        } else {
            int r = n - 2 * D_DIM;
            float acc = 0.f;
#pragma unroll
            for (int j = 0; j < RANK; j++)
                acc += B1[r * RANK + j] * A1[j * K_TOT + k];
            w += s1p[0] * acc;
        }
    }
    g_Wd[idx] = w;
}

// ---------------------------------------------------------------------------
// TF32 GEMM: C[M,N] = A[M,K] * Wd[N,K]^T + bias
// ---------------------------------------------------------------------------
__device__ __forceinline__ uint32_t f2tf32(float x) {
    uint32_t r;
    asm("cvt.rna.tf32.f32 %0, %1;" : "=r"(r) : "f"(x));
    return r;
}

__global__ __launch_bounds__(256, 1)
void gemm_tf32(const float* __restrict__ A,
               const float* __restrict__ bias,
               float* __restrict__ C)
{
    extern __shared__ float smem[];
    float* As = smem;               // 2 stages * ASZ
    float* Bs = smem + 2 * ASZ;     // 2 stages * ASZ

    const int tid  = threadIdx.x;
    const int warp = tid >> 5;
    const int lane = tid & 31;
    const int wm = warp >> 2;       // 0..1  (64-row band)
    const int wn = warp & 3;        // 0..3  (32-col band)
    const int qr = lane >> 2;       // 0..7
    const int qc = lane & 3;        // 0..3

    const int m0 = blockIdx.y * BM;
    const int n0 = blockIdx.x * BN;

    // cp.async producer mapping: 16B per thread, 8 threads per 32-float row
    const int lrow = tid >> 3;              // 0..31
    const int lcol = (tid & 7) << 2;        // float offset in row

    const float* gA = A    + (size_t)(m0 + lrow) * K_TOT + lcol;
    const float* gB = g_Wd + (size_t)(n0 + lrow) * K_TOT + lcol;

    const uint32_t sA0 = (uint32_t)__cvta_generic_to_shared(&As[lrow * STRIDE + lcol]);
    const uint32_t sB0 = (uint32_t)__cvta_generic_to_shared(&Bs[lrow * STRIDE + lcol]);

    float acc[4][4][4];
#pragma unroll
    for (int i = 0; i < 4; i++)
#pragma unroll
        for (int j = 0; j < 4; j++)
#pragma unroll
            for (int c = 0; c < 4; c++) acc[i][j][c] = 0.f;

    auto load_stage = [&](int s, int kt) {
        const int k0 = kt * BK;
        const uint32_t sbase_a = sA0 + (uint32_t)(s * ASZ * 4);
        const uint32_t sbase_b = sB0 + (uint32_t)(s * ASZ * 4);
#pragma unroll
        for (int i = 0; i < 4; i++) {
            asm volatile("cp.async.cg.shared.global [%0], [%1], 16;"
                         :: "r"(sbase_a + (uint32_t)(i * 32 * STRIDE * 4)),
                            "l"(gA + (size_t)i * 32 * K_TOT + k0));
            asm volatile("cp.async.cg.shared.global [%0], [%1], 16;"
                         :: "r"(sbase_b + (uint32_t)(i * 32 * STRIDE * 4)),
                            "l"(gB + (size_t)i * 32 * K_TOT + k0));
        }
        asm volatile("cp.async.commit_group;");
    };

    constexpr int NT = K_TOT / BK;  // 32
    load_stage(0, 0);

    for (int kt = 0; kt < NT; kt++) {
        if (kt + 1 < NT) {
            load_stage((kt + 1) & 1, kt + 1);
            asm volatile("cp.async.wait_group 1;");
        } else {
            asm volatile("cp.async.wait_group 0;");
        }
        __syncthreads();

        const float* a_tile = &As[(kt & 1) * ASZ];
        const float* b_tile = &Bs[(kt & 1) * ASZ];

#pragma unroll
        for (int kk = 0; kk < BK / 8; kk++) {
            const int k8 = kk * 8;
            uint32_t af[4][4], bf[4][2];
#pragma unroll
            for (int mt = 0; mt < 4; mt++) {
                const int br = wm * 64 + mt * 16;
                af[mt][0] = f2tf32(a_tile[(br + qr)     * STRIDE + k8 + qc]);
                af[mt][1] = f2tf32(a_tile[(br + qr + 8) * STRIDE + k8 + qc]);
                af[mt][2] = f2tf32(a_tile[(br + qr)     * STRIDE + k8 + qc + 4]);
                af[mt][3] = f2tf32(a_tile[(br + qr + 8) * STRIDE + k8 + qc + 4]);
            }
#pragma unroll
            for (int nt = 0; nt < 4; nt++) {
                const int bn = wn * 32 + nt * 8;
                bf[nt][0] = f2tf32(b_tile[(bn + qr) * STRIDE + k8 + qc]);
                bf[nt][1] = f2tf32(b_tile[(bn + qr) * STRIDE + k8 + qc + 4]);
            }
#pragma unroll
            for (int mt = 0; mt < 4; mt++)
#pragma unroll
                for (int nt = 0; nt < 4; nt++) {
                    asm volatile(
                        "mma.sync.aligned.m16n8k8.row.col.f32.tf32.tf32.f32 "
                        "{%0,%1,%2,%3},{%4,%5,%6,%7},{%8,%9},{%0,%1,%2,%3};"
                        : "+f"(acc[mt][nt][0]), "+f"(acc[mt][nt][1]),
                          "+f"(acc[mt][nt][2]), "+f"(acc[mt][nt][3])
                        : "r"(af[mt][0]), "r"(af[mt][1]), "r"(af[mt][2]), "r"(af[mt][3]),
                          "r"(bf[nt][0]), "r"(bf[nt][1]));
                }
        }
        __syncthreads();
    }

    // Epilogue: +bias, store fp32
#pragma unroll
    for (int mt = 0; mt < 4; mt++) {
        const int row0 = m0 + wm * 64 + mt * 16 + qr;
#pragma unroll
        for (int nt = 0; nt < 4; nt++) {
            const int col0 = n0 + wn * 32 + nt * 8 + qc * 2;
            const float b0v = bias[col0];
            const float b1v = bias[col0 + 1];
            C[(size_t)row0 * N_TOT + col0]           = acc[mt][nt][0] + b0v;
            C[(size_t)row0 * N_TOT + col0 + 1]       = acc[mt][nt][1] + b1v;
            C[(size_t)(row0 + 8) * N_TOT + col0]     = acc[mt][nt][2] + b0v;
            C[(size_t)(row0 + 8) * N_TOT + col0 + 1] = acc[mt][nt][3] + b1v;
        }
    }
}

// ---------------------------------------------------------------------------
extern "C" void kernel_launch(void* const* d_in, const int* in_sizes, int n_in,
                              void* d_out, int out_size)
{
    const float* x    = (const float*)d_in[0];
    const float* W    = (const float*)d_in[1];
    const float* bias = (const float*)d_in[2];
    const float* A0   = (const float*)d_in[3];
    const float* A1   = (const float*)d_in[4];
    const float* B0   = (const float*)d_in[5];
    const float* B1   = (const float*)d_in[6];
    const float* s0   = (const float*)d_in[7];
    const float* s1   = (const float*)d_in[8];
    float* out = (float*)d_out;

    (void)in_sizes; (void)n_in; (void)out_size;

    // 1) Materialize W + LoRA delta into the device-global weight buffer.
    prep_wd<<<(N_TOT * K_TOT + 255) / 256, 256>>>(W, A0, A1, B0, B1, s0, s1);

    // 2) TF32 tensor-core GEMM with fused bias.
    cudaFuncSetAttribute(gemm_tf32, cudaFuncAttributeMaxDynamicSharedMemorySize,
                         SMEM_BYTES);
    dim3 grid(N_TOT / BN, M_TOT / BM);   // x = N tiles (fast) for L2 reuse of A
    gemm_tf32<<<grid, 256, SMEM_BYTES>>>(x, bias, out);
}